// round 2
// baseline (speedup 1.0000x reference)
#include <cuda_runtime.h>

#define B 64
#define CHI 20
#define D 65536  // 64*32*32

// scratch for raw scores (pre-softmax), B*CHI floats
__device__ float g_scores[B * CHI];

// ---------------------------------------------------------------------------
// Kernel 1: scores[b,c] = sum_d x[b, c*D + d] * x[b, 19*D + d]
// One block per (b,c). 512 threads, float4 streaming, warp+block reduction.
// ---------------------------------------------------------------------------
__global__ __launch_bounds__(512) void scores_kernel(const float* __restrict__ x,
                                                     float* __restrict__ scores) {
    const int bc = blockIdx.x;
    const int b = bc / CHI;
    const int c = bc % CHI;

    const float4* __restrict__ last =
        reinterpret_cast<const float4*>(x + (size_t)b * CHI * D + (size_t)(CHI - 1) * D);
    const float4* __restrict__ fr =
        reinterpret_cast<const float4*>(x + (size_t)b * CHI * D + (size_t)c * D);

    float acc = 0.0f;
    const int n4 = D / 4;  // 16384
    #pragma unroll 4
    for (int i = threadIdx.x; i < n4; i += 512) {
        float4 l = last[i];
        float4 f = fr[i];
        acc = fmaf(l.x, f.x, acc);
        acc = fmaf(l.y, f.y, acc);
        acc = fmaf(l.z, f.z, acc);
        acc = fmaf(l.w, f.w, acc);
    }

    // warp reduce
    #pragma unroll
    for (int o = 16; o; o >>= 1) acc += __shfl_xor_sync(0xFFFFFFFFu, acc, o);

    __shared__ float sred[16];
    const int warp = threadIdx.x >> 5;
    const int lane = threadIdx.x & 31;
    if (lane == 0) sred[warp] = acc;
    __syncthreads();
    if (warp == 0) {
        acc = (lane < 16) ? sred[lane] : 0.0f;
        #pragma unroll
        for (int o = 8; o; o >>= 1) acc += __shfl_xor_sync(0xFFFFFFFFu, acc, o);
        if (lane == 0) scores[bc] = acc;
    }
}

// ---------------------------------------------------------------------------
// Kernel 2: out[b,d] = sum_c x[b, d*20 + c] * alpha[b,c]
// Softmax over the 20 scores recomputed per block (cheap, avoids a 3rd kernel).
// Each thread: one d, 5 aligned float4 loads (80 contiguous bytes).
// Grid: (D/256, B), block 256.
// ---------------------------------------------------------------------------
__global__ __launch_bounds__(256) void out_kernel(const float* __restrict__ x,
                                                  const float* __restrict__ scores,
                                                  float* __restrict__ out) {
    const int b = blockIdx.y;

    __shared__ float alpha[CHI];
    if (threadIdx.x == 0) {
        float s[CHI];
        float m = -1e30f;
        #pragma unroll
        for (int c = 0; c < CHI; c++) {
            s[c] = scores[b * CHI + c] * (1.0f / CHI);
            m = fmaxf(m, s[c]);
        }
        float sum = 0.0f;
        #pragma unroll
        for (int c = 0; c < CHI; c++) {
            s[c] = expf(s[c] - m);
            sum += s[c];
        }
        const float inv = 1.0f / sum;
        #pragma unroll
        for (int c = 0; c < CHI; c++) alpha[c] = s[c] * inv;
    }
    __syncthreads();

    float a[CHI];
    #pragma unroll
    for (int c = 0; c < CHI; c++) a[c] = alpha[c];

    const int d = blockIdx.x * 256 + threadIdx.x;
    const float4* __restrict__ p =
        reinterpret_cast<const float4*>(x + (size_t)b * CHI * D + (size_t)d * CHI);

    float acc = 0.0f;
    #pragma unroll
    for (int i = 0; i < 5; i++) {
        float4 v = p[i];
        acc = fmaf(v.x, a[4 * i + 0], acc);
        acc = fmaf(v.y, a[4 * i + 1], acc);
        acc = fmaf(v.z, a[4 * i + 2], acc);
        acc = fmaf(v.w, a[4 * i + 3], acc);
    }
    out[(size_t)b * D + d] = acc;
}

extern "C" void kernel_launch(void* const* d_in, const int* in_sizes, int n_in,
                              void* d_out, int out_size) {
    const float* x = (const float*)d_in[0];
    float* out = (float*)d_out;

    float* scores;
    cudaGetSymbolAddress((void**)&scores, g_scores);

    scores_kernel<<<B * CHI, 512>>>(x, scores);
    out_kernel<<<dim3(D / 256, B), 256>>>(x, scores, out);
}